// round 4
// baseline (speedup 1.0000x reference)
#include <cuda_runtime.h>
#include <cuda_bf16.h>
#include <cstdint>

// =============================================================================
// RAFF_8555574853896 — round 4: HMMA split-bf16 GEMMs with term-major MMA
// ordering (ILP fix), 4-stage cp.async pipeline, fused classifier epilogue,
// fused conversions.
//
// Algebra (validated):
//   scores = q Mt^T q^T / sqrt(D) + rank-1 bias,  Mt = (Wq^T Wk)^T
//   audio  = (w_a^T q) Cov^T + bcomb,             Cov = out_w Wv
// Split: x = hi + lo (bf16); A*B ~= Ahi*Bhi + Ahi*Blo + Alo*Bhi  (~1e-5)
// =============================================================================

namespace raff {

constexpr int B = 2048, S = 32, P = 16, D = 1024, H = 512, F = 512;
constexpr long NQ = (long)B * S * D;

// ---------------- static device scratch ----------------
__device__ float g_vq[D], g_vk[D], g_bcomb[D];
__device__ float g_c0;
__device__ float g_MC[2 * D * D];              // [Mt; Cov]
__device__ float g_qM[NQ];                     // 256 MB
__device__ float g_d[B * S];                   // classifier logits (atomic acc)
__device__ float g_av[2L * B * D];             // audio, video
__device__ float g_y[3L * B * F];              // pre-LN head outputs
__device__ float g_hbias[3 * F];               // packed head biases

__device__ __nv_bfloat16 g_q_hi[NQ], g_q_lo[NQ];
__device__ __nv_bfloat16 g_w1_hi[(long)S * H * D], g_w1_lo[(long)S * H * D];
__device__ __nv_bfloat16 g_u_hi[2 * D * D], g_u_lo[2 * D * D];   // [WkT; out_w]
__device__ __nv_bfloat16 g_v_hi[2 * D * D], g_v_lo[2 * D * D];   // [WqT; WvT]
__device__ __nv_bfloat16 g_mc_hi[2 * D * D], g_mc_lo[2 * D * D]; // [Mt; Cov]
__device__ __nv_bfloat16 g_qv_hi[2L * B * D], g_qv_lo[2L * B * D];
__device__ __nv_bfloat16 g_x_hi[3L * B * D], g_x_lo[3L * B * D]; // fus,aud,vid
__device__ __nv_bfloat16 g_hw_hi[3L * F * D], g_hw_lo[3L * F * D];

// ---------------- PTX helpers (base sm_103-legal) ----------------
__device__ __forceinline__ uint32_t smem_u32(const void* p) {
    uint32_t a;
    asm("{ .reg .u64 t; cvta.to.shared.u64 t, %1; cvt.u32.u64 %0, t; }"
        : "=r"(a) : "l"(p));
    return a;
}
#define CP16(dst, src) \
    asm volatile("cp.async.cg.shared.global [%0], [%1], 16;" :: "r"(dst), "l"(src))
#define CP_COMMIT() asm volatile("cp.async.commit_group;" ::: "memory")

__device__ __forceinline__ void ldsm_x4(uint32_t* r, uint32_t addr) {
    asm volatile("ldmatrix.sync.aligned.m8n8.x4.shared.b16 {%0,%1,%2,%3}, [%4];"
                 : "=r"(r[0]), "=r"(r[1]), "=r"(r[2]), "=r"(r[3]) : "r"(addr));
}
__device__ __forceinline__ void ldsm_x2(uint32_t* r, uint32_t addr) {
    asm volatile("ldmatrix.sync.aligned.m8n8.x2.shared.b16 {%0,%1}, [%2];"
                 : "=r"(r[0]), "=r"(r[1]) : "r"(addr));
}
__device__ __forceinline__ void mma_bf16(float* c, const uint32_t* a, const uint32_t* b) {
    asm volatile(
        "mma.sync.aligned.m16n8k16.row.col.f32.bf16.bf16.f32 "
        "{%0,%1,%2,%3}, {%4,%5,%6,%7}, {%8,%9}, {%0,%1,%2,%3};"
        : "+f"(c[0]), "+f"(c[1]), "+f"(c[2]), "+f"(c[3])
        : "r"(a[0]), "r"(a[1]), "r"(a[2]), "r"(a[3]), "r"(b[0]), "r"(b[1]));
}

// Swizzled tile address: rows of 64B (32 bf16), 4 x 16B chunks.
__device__ __forceinline__ uint32_t swz(int r, int c) {
    return (uint32_t)((r * 4 + (c ^ ((r >> 1) & 3))) * 16);
}

// =============================================================================
// HMMA split-bf16 GEMM: C[M,N] = A[M,K]*B[N,K]^T (+bias[n]) (+relu), fp32 out
// K = 1024. Block tile 128x128x32, 8 warps (2m x 4n), 4-stage cp.async.
// CLSD: instead of storing C, compute partial d = relu(C+bias).w2 and
//       atomicAdd into C (g_d), row index = m*S + z.
// =============================================================================
constexpr int STAGE = 32768;                 // Ahi 8K | Alo 8K | Bhi 8K | Blo 8K
constexpr int NSTG = 4;
constexpr int GEMM_SMEM = NSTG * STAGE;      // 128 KB

template <bool RELU, bool BIAS, bool CLSD>
__global__ void __launch_bounds__(256) bsgemm(
    const __nv_bfloat16* __restrict__ Ahi, const __nv_bfloat16* __restrict__ Alo,
    long lda, long aOffZ,
    const __nv_bfloat16* __restrict__ Bhi, const __nv_bfloat16* __restrict__ Blo,
    long bOffZ,
    float* __restrict__ C, int ldc, long cOffZ,
    const float* __restrict__ bias, long biasOffZ,
    const float* __restrict__ w2p)
{
    extern __shared__ char dsm[];
    const uint32_t base = smem_u32(dsm);

    const int tid = threadIdx.x, lane = tid & 31, w = tid >> 5;
    const int wm = w & 1, wn = w >> 1;            // 2 x 4 warp grid
    const int z = blockIdx.z;
    const long m0 = (long)blockIdx.y * 128;
    const long n0 = (long)blockIdx.x * 128;
    Ahi += z * aOffZ; Alo += z * aOffZ;
    Bhi += z * bOffZ; Blo += z * bOffZ;
    C += z * cOffZ;
    if (BIAS || CLSD) bias += z * biasOffZ;

    float acc[4][4][4];
#pragma unroll
    for (int i = 0; i < 4; i++)
#pragma unroll
        for (int j = 0; j < 4; j++)
#pragma unroll
            for (int k = 0; k < 4; k++) acc[i][j][k] = 0.f;

    // ---- cp.async tile loader: one K-chunk of 32 into stage s ----
    auto loadChunk = [&](int s, int kc) {
        const long k0 = (long)kc * 32;
        const uint32_t ah = base + s * STAGE;
        const uint32_t al = ah + 8192;
        const uint32_t bh = ah + 16384;
        const uint32_t bl = ah + 24576;
#pragma unroll
        for (int i = 0; i < 2; i++) {
            const int idx = tid + 256 * i;
            const int r = idx >> 2, c = idx & 3;
            const uint32_t dst = swz(r, c);
            const long offA = (m0 + r) * lda + k0 + c * 8;
            CP16(ah + dst, Ahi + offA);
            CP16(al + dst, Alo + offA);
            const long offB = (n0 + r) * 1024 + k0 + c * 8;
            CP16(bh + dst, Bhi + offB);
            CP16(bl + dst, Blo + offB);
        }
        CP_COMMIT();
    };

    // ---- compute one chunk, term-major (no per-acc serial chains) ----
    auto computeChunk = [&](int s) {
        const uint32_t ah = base + s * STAGE;
        const uint32_t al = ah + 8192;
        const uint32_t bh = ah + 16384;
        const uint32_t bl = ah + 24576;
#pragma unroll
        for (int ks = 0; ks < 2; ks++) {
            uint32_t afh[4][4], afl[4][4], bfh[4][2], bfl[4][2];
            const int arow = wm * 64 + (lane & 15);
            const int akc = ks * 2 + (lane >> 4);
#pragma unroll
            for (int i = 0; i < 4; i++) {
                const uint32_t off = swz(arow + i * 16, akc);
                ldsm_x4(afh[i], ah + off);
                ldsm_x4(afl[i], al + off);
            }
            const int brow = wn * 32 + (lane & 7);
            const int bkc = ks * 2 + ((lane >> 3) & 1);
#pragma unroll
            for (int j = 0; j < 4; j++) {
                const uint32_t off = swz(brow + j * 8, bkc);
                ldsm_x2(bfh[j], bh + off);
                ldsm_x2(bfl[j], bl + off);
            }
#pragma unroll
            for (int i = 0; i < 4; i++)
#pragma unroll
                for (int j = 0; j < 4; j++) mma_bf16(acc[i][j], afh[i], bfh[j]);
#pragma unroll
            for (int i = 0; i < 4; i++)
#pragma unroll
                for (int j = 0; j < 4; j++) mma_bf16(acc[i][j], afh[i], bfl[j]);
#pragma unroll
            for (int i = 0; i < 4; i++)
#pragma unroll
                for (int j = 0; j < 4; j++) mma_bf16(acc[i][j], afl[i], bfh[j]);
        }
    };

    loadChunk(0, 0);
    loadChunk(1, 1);
    loadChunk(2, 2);

    for (int ch = 0; ch < 32; ch++) {
        asm volatile("cp.async.wait_group 2;" ::: "memory");
        __syncthreads();
        if (ch + 3 < 32) loadChunk((ch + 3) & 3, ch + 3);
        else CP_COMMIT();                       // keep wait_group count valid
        computeChunk(ch & 3);
    }

    const int gr = lane >> 2, qd = lane & 3;

    if (CLSD) {
        // ---- fused classifier layer 2: partial d += relu(acc+b1).w2 ----
        float p[4][2];
#pragma unroll
        for (int i = 0; i < 4; i++) { p[i][0] = 0.f; p[i][1] = 0.f; }
        const float* w2 = w2p + (long)z * H;
#pragma unroll
        for (int j = 0; j < 4; j++) {
            const long c = n0 + wn * 32 + j * 8 + qd * 2;
            const float2 w2v = *(const float2*)&w2[c];
            const float2 bv = *(const float2*)&bias[c];
#pragma unroll
            for (int i = 0; i < 4; i++) {
                const float h0 = fmaxf(acc[i][j][0] + bv.x, 0.f);
                const float h1 = fmaxf(acc[i][j][1] + bv.y, 0.f);
                p[i][0] += h0 * w2v.x + h1 * w2v.y;
                const float h2 = fmaxf(acc[i][j][2] + bv.x, 0.f);
                const float h3 = fmaxf(acc[i][j][3] + bv.y, 0.f);
                p[i][1] += h2 * w2v.x + h3 * w2v.y;
            }
        }
#pragma unroll
        for (int i = 0; i < 4; i++) {
            p[i][0] += __shfl_xor_sync(~0u, p[i][0], 1);
            p[i][0] += __shfl_xor_sync(~0u, p[i][0], 2);
            p[i][1] += __shfl_xor_sync(~0u, p[i][1], 1);
            p[i][1] += __shfl_xor_sync(~0u, p[i][1], 2);
            if (qd == 0) {
                const long r = m0 + wm * 64 + i * 16 + gr;
                atomicAdd(&C[r * S + z], p[i][0]);
                atomicAdd(&C[(r + 8) * S + z], p[i][1]);
            }
        }
    } else {
        // ---- standard epilogue ----
#pragma unroll
        for (int j = 0; j < 4; j++) {
            const long c = n0 + wn * 32 + j * 8 + qd * 2;
            float2 bv = make_float2(0.f, 0.f);
            if (BIAS) bv = *(const float2*)&bias[c];
#pragma unroll
            for (int i = 0; i < 4; i++) {
                const long r0 = m0 + wm * 64 + i * 16 + gr;
                float2 v0 = make_float2(acc[i][j][0] + bv.x, acc[i][j][1] + bv.y);
                float2 v1 = make_float2(acc[i][j][2] + bv.x, acc[i][j][3] + bv.y);
                if (RELU) {
                    v0.x = fmaxf(v0.x, 0.f); v0.y = fmaxf(v0.y, 0.f);
                    v1.x = fmaxf(v1.x, 0.f); v1.y = fmaxf(v1.y, 0.f);
                }
                *(float2*)&C[r0 * ldc + c] = v0;
                *(float2*)&C[(r0 + 8) * ldc + c] = v1;
            }
        }
    }
}

// =============================================================================
// fp32 -> bf16 hi/lo split (vectorized by 4)
// =============================================================================
__device__ __forceinline__ void store_split4(float4 v, __nv_bfloat16* hi,
                                             __nv_bfloat16* lo, long i4) {
    __nv_bfloat16 h0 = __float2bfloat16(v.x), h1 = __float2bfloat16(v.y);
    __nv_bfloat16 h2 = __float2bfloat16(v.z), h3 = __float2bfloat16(v.w);
    __nv_bfloat162 a, b;
    a.x = h0; a.y = h1; b.x = h2; b.y = h3;
    ((__nv_bfloat162*)hi)[2 * i4] = a; ((__nv_bfloat162*)hi)[2 * i4 + 1] = b;
    a.x = __float2bfloat16(v.x - __bfloat162float(h0));
    a.y = __float2bfloat16(v.y - __bfloat162float(h1));
    b.x = __float2bfloat16(v.z - __bfloat162float(h2));
    b.y = __float2bfloat16(v.w - __bfloat162float(h3));
    ((__nv_bfloat162*)lo)[2 * i4] = a; ((__nv_bfloat162*)lo)[2 * i4 + 1] = b;
}

__global__ void split4(const float* __restrict__ src, __nv_bfloat16* __restrict__ hi,
                       __nv_bfloat16* __restrict__ lo, long n4)
{
    const long i = (long)blockIdx.x * 256 + threadIdx.x;
    if (i >= n4) return;
    store_split4(((const float4*)src)[i], hi, lo, i);
}

// 1024x1024 transpose + split: dst[c][r] = src[r][c]
__global__ void tsplit(const float* __restrict__ src, __nv_bfloat16* __restrict__ hi,
                       __nv_bfloat16* __restrict__ lo)
{
    __shared__ float t[32][33];
    const int bx = blockIdx.x * 32, by = blockIdx.y * 32;
    const int tx = threadIdx.x;
    for (int j = threadIdx.y; j < 32; j += 8)
        t[j][tx] = src[(long)(by + j) * 1024 + bx + tx];
    __syncthreads();
    for (int j = threadIdx.y; j < 32; j += 8) {
        const float v = t[tx][j];
        const long o = (long)(bx + j) * 1024 + by + tx;
        __nv_bfloat16 h = __float2bfloat16(v);
        hi[o] = h;
        lo[o] = __float2bfloat16(v - __bfloat162float(h));
    }
}

// avsplit: fusion = 0.5*(audio+video); split fusion, audio, video -> x hi/lo
__global__ void avsplit()
{
    const long i = (long)blockIdx.x * 256 + threadIdx.x;
    const long n4 = (long)B * D / 4;
    float4 a = ((const float4*)g_av)[i];
    float4 v = ((const float4*)g_av)[n4 + i];
    float4 f = make_float4(0.5f * (a.x + v.x), 0.5f * (a.y + v.y),
                           0.5f * (a.z + v.z), 0.5f * (a.w + v.w));
    store_split4(f, g_x_hi, g_x_lo, i);
    store_split4(a, g_x_hi, g_x_lo, n4 + i);
    store_split4(v, g_x_hi, g_x_lo, 2 * n4 + i);
}

__global__ void zero_d()
{
    g_d[blockIdx.x * 256 + threadIdx.x] = 0.f;
}

__global__ void pack_bias(const float* __restrict__ b0, const float* __restrict__ b1,
                          const float* __restrict__ b2)
{
    const int i = blockIdx.x * 256 + threadIdx.x;   // 0..1535
    const int hh = i >> 9, j = i & 511;
    g_hbias[i] = hh == 0 ? b0[j] : (hh == 1 ? b1[j] : b2[j]);
}

// =============================================================================
// bias-derived vectors (fp32, tiny)
// =============================================================================
__global__ void vec_pre(const float* __restrict__ in_proj_w,
                        const float* __restrict__ in_proj_b,
                        const float* __restrict__ out_w,
                        const float* __restrict__ out_b)
{
    const int i = blockIdx.x * 256 + threadIdx.x;
    const float* wq = in_proj_w;
    const float* wk = in_proj_w + (long)D * D;
    const float* bq = in_proj_b;
    const float* bk = in_proj_b + D;
    const float* bv = in_proj_b + 2 * D;
    float vq = 0.f, vk = 0.f, bc = 0.f;
    for (int e = 0; e < D; e++) {
        vq = fmaf(bq[e], wk[(long)e * D + i], vq);
        vk = fmaf(bk[e], wq[(long)e * D + i], vk);
        bc = fmaf(out_w[(long)i * D + e], bv[e], bc);
    }
    g_vq[i] = vq; g_vk[i] = vk; g_bcomb[i] = bc + out_b[i];
    if (i == 0) {
        float c = 0.f;
        for (int e = 0; e < D; e++) c = fmaf(bq[e], bk[e], c);
        g_c0 = c;
    }
}

// =============================================================================
// Per-batch attention (fp32); reads g_d (pre-bias logits), writes qv hi/lo
// =============================================================================
__global__ void __launch_bounds__(256) attn_kernel(
    const float* __restrict__ q, const float* __restrict__ cls_b2,
    float* __restrict__ out)
{
    const int b = blockIdx.x;
    __shared__ float qs[32][132];
    __shared__ float qms[32][132];
    __shared__ float sc[32][33];
    __shared__ float vks[128];
    __shared__ float dd[32], rk[32], wa[32], wvv[32], da[16], dv[16];

    const int tid = threadIdx.x;
    const int s = tid >> 3;
    const int tb = tid & 7;
    const float* qb = q + (long)b * S * D;
    const float* qmb = g_qM + (long)b * S * D;

    if (tid < 32) dd[tid] = fmaxf(g_d[b * S + tid] + cls_b2[tid], 0.f);

    float racc[4] = {0.f, 0.f, 0.f, 0.f};
    float rkacc = 0.f;

    for (int c = 0; c < D; c += 128) {
#pragma unroll
        for (int i = 0; i < 4; i++) {
            const int f = tid + 256 * i;
            const int r = f >> 5;
            const int c4 = (f & 31) << 2;
            *(float4*)&qs[r][c4] = *(const float4*)&qb[(long)r * D + c + c4];
            *(float4*)&qms[r][c4] = *(const float4*)&qmb[(long)r * D + c + c4];
        }
        if (tid < 32) *(float4*)&vks[tid * 4] = *(const float4*)&g_vk[c + tid * 4];
        __syncthreads();

#pragma unroll 4
        for (int k = 0; k < 128; k++) {
            const float av = qms[s][k];
#pragma unroll
            for (int j = 0; j < 4; j++)
                racc[j] = fmaf(av, qs[tb + 8 * j][k], racc[j]);
        }
        if (tid < 32) {
            float r2 = 0.f;
#pragma unroll 4
            for (int k = 0; k < 128; k++) r2 = fmaf(qs[tid][k], vks[k], r2);
            rkacc += r2;
        }
        __syncthreads();
    }

#pragma unroll
    for (int j = 0; j < 4; j++) sc[s][tb + 8 * j] = racc[j];
    if (tid < 32) rk[tid] = rkacc;
    __syncthreads();

    const int w = tid >> 5, lane = tid & 31;
    const float inv_sqrtD = 0.03125f;
    for (int rr = w * 4; rr < w * 4 + 4; rr++) {
        float v = (sc[rr][lane] + rk[rr] + g_c0) * inv_sqrtD;
        float mx = v;
#pragma unroll
        for (int o = 16; o > 0; o >>= 1) mx = fmaxf(mx, __shfl_xor_sync(~0u, mx, o));
        float e = __expf(v - mx);
        float sum = e;
#pragma unroll
        for (int o = 16; o > 0; o >>= 1) sum += __shfl_xor_sync(~0u, sum, o);
        sc[rr][lane] = e / sum;
    }
    __syncthreads();

    if (tid < 32) {
        const bool isA = tid < 16;
        const int i = tid & 15;
        float v = dd[tid];
        float mx = v;
#pragma unroll
        for (int o = 8; o > 0; o >>= 1) mx = fmaxf(mx, __shfl_xor_sync(~0u, mx, o));
        float e = __expf(v - mx);
        float sum = e;
#pragma unroll
        for (int o = 8; o > 0; o >>= 1) sum += __shfl_xor_sync(~0u, sum, o);
        const float p = e / sum;
        if (isA) da[i] = p; else dv[i] = p;
        const long bse = 3L * B * F;
        if (isA) out[bse + (long)b * P + i] = p;
        else     out[bse + (long)B * P + (long)b * P + i] = p;
    }
    __syncthreads();

    if (tid < 32) {
        float a = 0.f, v2 = 0.f;
#pragma unroll
        for (int ss = 0; ss < 16; ss++) a = fmaf(da[ss], sc[ss][tid], a);
#pragma unroll
        for (int ss = 0; ss < 16; ss++) v2 = fmaf(dv[ss], sc[16 + ss][tid], v2);
        wa[tid] = a;
        wvv[tid] = v2;
    }
    __syncthreads();

#pragma unroll
    for (int i = 0; i < 4; i++) {
        const int col = tid + 256 * i;
        float a = 0.f, v2 = 0.f;
#pragma unroll
        for (int t = 0; t < 32; t++) {
            const float x = qb[(long)t * D + col];
            a = fmaf(wa[t], x, a);
            v2 = fmaf(wvv[t], x, v2);
        }
        const long ia = (long)b * D + col;
        const long iv = (long)B * D + ia;
        __nv_bfloat16 h = __float2bfloat16(a);
        g_qv_hi[ia] = h;
        g_qv_lo[ia] = __float2bfloat16(a - __bfloat162float(h));
        h = __float2bfloat16(v2);
        g_qv_hi[iv] = h;
        g_qv_lo[iv] = __float2bfloat16(v2 - __bfloat162float(h));
    }
}

__global__ void __launch_bounds__(128) ln_relu(
    const float* __restrict__ gm0, const float* __restrict__ be0,
    const float* __restrict__ gm1, const float* __restrict__ be1,
    const float* __restrict__ gm2, const float* __restrict__ be2,
    float* __restrict__ out)
{
    const int head = blockIdx.y, b = blockIdx.x, tid = threadIdx.x;
    const float* gm = head == 0 ? gm0 : (head == 1 ? gm1 : gm2);
    const float* be = head == 0 ? be0 : (head == 1 ? be1 : be2);
    const float* y = g_y + ((long)head * B + b) * F;

    float4 v = *(const float4*)&y[tid * 4];
    float s = v.x + v.y + v.z + v.w;
    float sq = v.x * v.x + v.y * v.y + v.z * v.z + v.w * v.w;
#pragma unroll
    for (int o = 16; o > 0; o >>= 1) {
        s += __shfl_xor_sync(~0u, s, o);
        sq += __shfl_xor_sync(~0u, sq, o);
    }
    __shared__ float ss[4], ssq[4];
    const int w = tid >> 5;
    if ((tid & 31) == 0) { ss[w] = s; ssq[w] = sq; }
    __syncthreads();
    s = ss[0] + ss[1] + ss[2] + ss[3];
    sq = ssq[0] + ssq[1] + ssq[2] + ssq[3];
    const float mean = s * (1.f / F);
    const float var = sq * (1.f / F) - mean * mean;
    const float rstd = rsqrtf(var + 1e-5f);

    float4 g4 = *(const float4*)&gm[tid * 4];
    float4 b4 = *(const float4*)&be[tid * 4];
    float4 o4;
    o4.x = fmaxf((v.x - mean) * rstd * g4.x + b4.x, 0.f);
    o4.y = fmaxf((v.y - mean) * rstd * g4.y + b4.y, 0.f);
    o4.z = fmaxf((v.z - mean) * rstd * g4.z + b4.z, 0.f);
    o4.w = fmaxf((v.w - mean) * rstd * g4.w + b4.w, 0.f);
    *(float4*)&out[((long)head * B + b) * F + tid * 4] = o4;
}

}  // namespace raff

// =============================================================================
// Launch
// =============================================================================
extern "C" void kernel_launch(void* const* d_in, const int* in_sizes, int n_in,
                              void* d_out, int out_size)
{
    using namespace raff;
    (void)in_sizes; (void)n_in; (void)out_size;

    const float* q         = (const float*)d_in[0];
    const float* in_proj_w = (const float*)d_in[1];
    const float* in_proj_b = (const float*)d_in[2];
    const float* out_w     = (const float*)d_in[3];
    const float* out_b     = (const float*)d_in[4];
    const float* cls_w1    = (const float*)d_in[5];
    const float* cls_b1    = (const float*)d_in[6];
    const float* cls_w2    = (const float*)d_in[7];
    const float* cls_b2    = (const float*)d_in[8];
    const float* fus_w     = (const float*)d_in[9];
    const float* fus_b     = (const float*)d_in[10];
    const float* fus_g     = (const float*)d_in[11];
    const float* fus_be    = (const float*)d_in[12];
    const float* pa_w      = (const float*)d_in[13];
    const float* pa_b      = (const float*)d_in[14];
    const float* pa_g      = (const float*)d_in[15];
    const float* pa_be     = (const float*)d_in[16];
    const float* pv_w      = (const float*)d_in[17];
    const float* pv_b      = (const float*)d_in[18];
    const float* pv_g      = (const float*)d_in[19];
    const float* pv_be     = (const float*)d_in[20];
    float* out = (float*)d_out;

    float *pMC, *pqM, *pd, *pav, *py, *pvq, *pbcomb, *phb;
    __nv_bfloat16 *qhi, *qlo, *w1hi, *w1lo, *uhi, *ulo, *vhi, *vlo,
        *mchi, *mclo, *qvhi, *qvlo, *xhi, *xlo, *hwhi, *hwlo;
    cudaGetSymbolAddress((void**)&pMC, g_MC);
    cudaGetSymbolAddress((void**)&pqM, g_qM);
    cudaGetSymbolAddress((void**)&pd, g_d);
    cudaGetSymbolAddress((void**)&pav, g_av);
    cudaGetSymbolAddress((void**)&py, g_y);
    cudaGetSymbolAddress((void**)&pvq, g_vq);
    cudaGetSymbolAddress((void**)&pbcomb, g_bcomb);
    cudaGetSymbolAddress((void**)&phb, g_hbias);
    cudaGetSymbolAddress((void**)&qhi, g_q_hi);
    cudaGetSymbolAddress((void**)&qlo, g_q_lo);
    cudaGetSymbolAddress((void**)&w1hi, g_w1_hi);
    cudaGetSymbolAddress((void**)&w1lo, g_w1_lo);
    cudaGetSymbolAddress((void**)&uhi, g_u_hi);
    cudaGetSymbolAddress((void**)&ulo, g_u_lo);
    cudaGetSymbolAddress((void**)&vhi, g_v_hi);
    cudaGetSymbolAddress((void**)&vlo, g_v_lo);
    cudaGetSymbolAddress((void**)&mchi, g_mc_hi);
    cudaGetSymbolAddress((void**)&mclo, g_mc_lo);
    cudaGetSymbolAddress((void**)&qvhi, g_qv_hi);
    cudaGetSymbolAddress((void**)&qvlo, g_qv_lo);
    cudaGetSymbolAddress((void**)&xhi, g_x_hi);
    cudaGetSymbolAddress((void**)&xlo, g_x_lo);
    cudaGetSymbolAddress((void**)&hwhi, g_hw_hi);
    cudaGetSymbolAddress((void**)&hwlo, g_hw_lo);

    cudaFuncSetAttribute((const void*)bsgemm<false, false, false>,
                         cudaFuncAttributeMaxDynamicSharedMemorySize, GEMM_SMEM);
    cudaFuncSetAttribute((const void*)bsgemm<false, true, false>,
                         cudaFuncAttributeMaxDynamicSharedMemorySize, GEMM_SMEM);
    cudaFuncSetAttribute((const void*)bsgemm<false, false, true>,
                         cudaFuncAttributeMaxDynamicSharedMemorySize, GEMM_SMEM);

    // 1) tiny precomputations
    vec_pre<<<D / 256, 256>>>(in_proj_w, in_proj_b, out_w, out_b);
    pack_bias<<<6, 256>>>(fus_b, pa_b, pv_b);
    zero_d<<<B * S / 256, 256>>>();

    // 2) conversions of inputs
    split4<<<(int)(NQ / 4 / 256), 256>>>(q, qhi, qlo, NQ / 4);
    split4<<<(int)((long)S * H * D / 4 / 256), 256>>>(cls_w1, w1hi, w1lo,
                                                      (long)S * H * D / 4);
    split4<<<D * D / 4 / 256, 256>>>(out_w, uhi + (long)D * D, ulo + (long)D * D,
                                     D * D / 4);
    split4<<<F * D / 4 / 256, 256>>>(fus_w, hwhi, hwlo, (long)F * D / 4);
    split4<<<F * D / 4 / 256, 256>>>(pa_w, hwhi + (long)F * D, hwlo + (long)F * D,
                                     (long)F * D / 4);
    split4<<<F * D / 4 / 256, 256>>>(pv_w, hwhi + 2L * F * D, hwlo + 2L * F * D,
                                     (long)F * D / 4);
    tsplit<<<dim3(32, 32), dim3(32, 8)>>>(in_proj_w + (long)D * D, uhi, ulo);    // WkT
    tsplit<<<dim3(32, 32), dim3(32, 8)>>>(in_proj_w, vhi, vlo);                  // WqT
    tsplit<<<dim3(32, 32), dim3(32, 8)>>>(in_proj_w + 2L * D * D,
                                          vhi + (long)D * D, vlo + (long)D * D); // WvT

    // 3) [Mt; Cov] in one z=2 launch: z0 = WkT*WqT^T, z1 = out_w*WvT^T
    bsgemm<false, false, false><<<dim3(8, 8, 2), 256, GEMM_SMEM>>>(
        uhi, ulo, D, (long)D * D, vhi, vlo, (long)D * D,
        pMC, D, (long)D * D, nullptr, 0L, nullptr);
    split4<<<2 * D * D / 4 / 256, 256>>>(pMC, mchi, mclo, 2 * D * D / 4);

    // 4) qM = q * Mt^T + vq   [65536 x 1024 x 1024]
    bsgemm<false, true, false><<<dim3(8, 512), 256, GEMM_SMEM>>>(
        qhi, qlo, (long)D, 0L, mchi, mclo, 0L, pqM, D, 0L, pvq, 0L, nullptr);

    // 5) classifier: fused h = relu(q w1^T + b1), d += h.w2 (atomic)
    bsgemm<false, false, true><<<dim3(4, 16, 32), 256, GEMM_SMEM>>>(
        qhi, qlo, (long)S * D, (long)D, w1hi, w1lo, (long)H * D,
        pd, S, 0L, cls_b1, (long)H, cls_w2);

    // 6) attention + softmaxes + weighted q sums -> qv hi/lo
    attn_kernel<<<B, 256>>>(q, cls_b2, out);

    // 7) [audio; video] = qv * Cov^T + bcomb
    bsgemm<false, true, false><<<dim3(8, 32), 256, GEMM_SMEM>>>(
        qvhi, qvlo, (long)D, 0L, mchi + (long)D * D, mclo + (long)D * D, 0L,
        pav, D, 0L, pbcomb, 0L, nullptr);

    // 8) fusion + splits of head inputs
    avsplit<<<(int)((long)B * D / 4 / 256), 256>>>();

    // 9) heads: one z=3 launch  y = x * W^T + b  [2048 x 512 x 1024]
    bsgemm<false, true, false><<<dim3(4, 16, 3), 256, GEMM_SMEM>>>(
        xhi, xlo, (long)D, (long)B * D, hwhi, hwlo, (long)F * D,
        py, F, (long)B * F, phb, (long)F, nullptr);

    // 10) LayerNorm + ReLU -> final outputs
    ln_relu<<<dim3(B, 3), 128>>>(fus_g, fus_be, pa_g, pa_be, pv_g, pv_be, out);
}

// round 7
// speedup vs baseline: 1.1272x; 1.1272x over previous
#include <cuda_runtime.h>
#include <cuda_bf16.h>
#include <cstdint>

// =============================================================================
// RAFF_8555574853896 — round 5: HMMA split-bf16 GEMMs, term-major MMA order,
// 3-stage cp.async pipeline @ 96KB smem, 2 blocks/SM (launch_bounds 256,2),
// race-free load ordering, fused classifier epilogue + fused conversions.
//
// Algebra (validated):
//   scores = q Mt^T q^T / sqrt(D) + rank-1 bias,  Mt = (Wq^T Wk)^T
//   audio  = (w_a^T q) Cov^T + bcomb,             Cov = out_w Wv
// Split: x = hi + lo (bf16); A*B ~= Ahi*Bhi + Ahi*Blo + Alo*Bhi  (~1e-5)
// =============================================================================

namespace raff {

constexpr int B = 2048, S = 32, P = 16, D = 1024, H = 512, F = 512;
constexpr long NQ = (long)B * S * D;

// ---------------- static device scratch ----------------
__device__ float g_vq[D], g_vk[D], g_bcomb[D];
__device__ float g_c0;
__device__ float g_MC[2 * D * D];              // [Mt; Cov]
__device__ float g_qM[NQ];                     // 256 MB
__device__ float g_d[B * S];                   // classifier logits (atomic acc)
__device__ float g_av[2L * B * D];             // audio, video
__device__ float g_y[3L * B * F];              // pre-LN head outputs
__device__ float g_hbias[3 * F];               // packed head biases

__device__ __nv_bfloat16 g_q_hi[NQ], g_q_lo[NQ];
__device__ __nv_bfloat16 g_w1_hi[(long)S * H * D], g_w1_lo[(long)S * H * D];
__device__ __nv_bfloat16 g_u_hi[2 * D * D], g_u_lo[2 * D * D];   // [WkT; out_w]
__device__ __nv_bfloat16 g_v_hi[2 * D * D], g_v_lo[2 * D * D];   // [WqT; WvT]
__device__ __nv_bfloat16 g_mc_hi[2 * D * D], g_mc_lo[2 * D * D]; // [Mt; Cov]
__device__ __nv_bfloat16 g_qv_hi[2L * B * D], g_qv_lo[2L * B * D];
__device__ __nv_bfloat16 g_x_hi[3L * B * D], g_x_lo[3L * B * D]; // fus,aud,vid
__device__ __nv_bfloat16 g_hw_hi[3L * F * D], g_hw_lo[3L * F * D];

// ---------------- PTX helpers (base sm_103-legal) ----------------
__device__ __forceinline__ uint32_t smem_u32(const void* p) {
    uint32_t a;
    asm("{ .reg .u64 t; cvta.to.shared.u64 t, %1; cvt.u32.u64 %0, t; }"
        : "=r"(a) : "l"(p));
    return a;
}
#define CP16(dst, src) \
    asm volatile("cp.async.cg.shared.global [%0], [%1], 16;" :: "r"(dst), "l"(src))
#define CP_COMMIT() asm volatile("cp.async.commit_group;" ::: "memory")

__device__ __forceinline__ void ldsm_x4(uint32_t* r, uint32_t addr) {
    asm volatile("ldmatrix.sync.aligned.m8n8.x4.shared.b16 {%0,%1,%2,%3}, [%4];"
                 : "=r"(r[0]), "=r"(r[1]), "=r"(r[2]), "=r"(r[3]) : "r"(addr));
}
__device__ __forceinline__ void ldsm_x2(uint32_t* r, uint32_t addr) {
    asm volatile("ldmatrix.sync.aligned.m8n8.x2.shared.b16 {%0,%1}, [%2];"
                 : "=r"(r[0]), "=r"(r[1]) : "r"(addr));
}
__device__ __forceinline__ void mma_bf16(float* c, const uint32_t* a, const uint32_t* b) {
    asm volatile(
        "mma.sync.aligned.m16n8k16.row.col.f32.bf16.bf16.f32 "
        "{%0,%1,%2,%3}, {%4,%5,%6,%7}, {%8,%9}, {%0,%1,%2,%3};"
        : "+f"(c[0]), "+f"(c[1]), "+f"(c[2]), "+f"(c[3])
        : "r"(a[0]), "r"(a[1]), "r"(a[2]), "r"(a[3]), "r"(b[0]), "r"(b[1]));
}

// Swizzled tile address: rows of 64B (32 bf16), 4 x 16B chunks.
__device__ __forceinline__ uint32_t swz(int r, int c) {
    return (uint32_t)((r * 4 + (c ^ ((r >> 1) & 3))) * 16);
}

// =============================================================================
// HMMA split-bf16 GEMM: C[M,N] = A[M,K]*B[N,K]^T (+bias[n]) (+relu), fp32 out
// K = 1024. Block tile 128x128x32, 8 warps (2m x 4n), 3-stage cp.async,
// 2 blocks/SM. CLSD: d = relu(C+bias).w2 partial dots, atomicAdd into C.
// =============================================================================
constexpr int STAGE = 32768;                 // Ahi 8K | Alo 8K | Bhi 8K | Blo 8K
constexpr int NSTG = 3;
constexpr int GEMM_SMEM = NSTG * STAGE;      // 96 KB -> 2 blocks/SM

template <bool RELU, bool BIAS, bool CLSD>
__global__ void __launch_bounds__(256, 2) bsgemm(
    const __nv_bfloat16* __restrict__ Ahi, const __nv_bfloat16* __restrict__ Alo,
    long lda, long aOffZ,
    const __nv_bfloat16* __restrict__ Bhi, const __nv_bfloat16* __restrict__ Blo,
    long bOffZ,
    float* __restrict__ C, int ldc, long cOffZ,
    const float* __restrict__ bias, long biasOffZ,
    const float* __restrict__ w2p)
{
    extern __shared__ char dsm[];
    const uint32_t base = smem_u32(dsm);

    const int tid = threadIdx.x, lane = tid & 31, w = tid >> 5;
    const int wm = w & 1, wn = w >> 1;            // 2 x 4 warp grid
    const int z = blockIdx.z;
    const long m0 = (long)blockIdx.y * 128;
    const long n0 = (long)blockIdx.x * 128;
    Ahi += z * aOffZ; Alo += z * aOffZ;
    Bhi += z * bOffZ; Blo += z * bOffZ;
    C += z * cOffZ;
    if (BIAS || CLSD) bias += z * biasOffZ;

    float acc[4][4][4];
#pragma unroll
    for (int i = 0; i < 4; i++)
#pragma unroll
        for (int j = 0; j < 4; j++)
#pragma unroll
            for (int k = 0; k < 4; k++) acc[i][j][k] = 0.f;

    // ---- cp.async tile loader: one K-chunk of 32 into stage s ----
    auto loadChunk = [&](int s, int kc) {
        const long k0 = (long)kc * 32;
        const uint32_t ah = base + s * STAGE;
        const uint32_t al = ah + 8192;
        const uint32_t bh = ah + 16384;
        const uint32_t bl = ah + 24576;
#pragma unroll
        for (int i = 0; i < 2; i++) {
            const int idx = tid + 256 * i;
            const int r = idx >> 2, c = idx & 3;
            const uint32_t dst = swz(r, c);
            const long offA = (m0 + r) * lda + k0 + c * 8;
            CP16(ah + dst, Ahi + offA);
            CP16(al + dst, Alo + offA);
            const long offB = (n0 + r) * 1024 + k0 + c * 8;
            CP16(bh + dst, Bhi + offB);
            CP16(bl + dst, Blo + offB);
        }
        CP_COMMIT();
    };

    // ---- compute one chunk, term-major, B frags reloaded (reg diet) ----
    auto computeChunk = [&](int s) {
        const uint32_t ah = base + s * STAGE;
        const uint32_t al = ah + 8192;
        const uint32_t bh = ah + 16384;
        const uint32_t bl = ah + 24576;
#pragma unroll
        for (int ks = 0; ks < 2; ks++) {
            uint32_t afh[4][4], afl[4][4], bf[4][2];
            const int arow = wm * 64 + (lane & 15);
            const int akc = ks * 2 + (lane >> 4);
#pragma unroll
            for (int i = 0; i < 4; i++) {
                const uint32_t off = swz(arow + i * 16, akc);
                ldsm_x4(afh[i], ah + off);
                ldsm_x4(afl[i], al + off);
            }
            const int brow = wn * 32 + (lane & 7);
            const int bkc = ks * 2 + ((lane >> 3) & 1);
#pragma unroll
            for (int j = 0; j < 4; j++)
                ldsm_x2(bf[j], bh + swz(brow + j * 8, bkc));
            // hh then lh (B-hi frags shared)
#pragma unroll
            for (int i = 0; i < 4; i++)
#pragma unroll
                for (int j = 0; j < 4; j++) mma_bf16(acc[i][j], afh[i], bf[j]);
#pragma unroll
            for (int i = 0; i < 4; i++)
#pragma unroll
                for (int j = 0; j < 4; j++) mma_bf16(acc[i][j], afl[i], bf[j]);
            // overwrite with B-lo frags, hl
#pragma unroll
            for (int j = 0; j < 4; j++)
                ldsm_x2(bf[j], bl + swz(brow + j * 8, bkc));
#pragma unroll
            for (int i = 0; i < 4; i++)
#pragma unroll
                for (int j = 0; j < 4; j++) mma_bf16(acc[i][j], afh[i], bf[j]);
        }
    };

    loadChunk(0, 0);
    loadChunk(1, 1);

    for (int ch = 0; ch < 32; ch++) {
        asm volatile("cp.async.wait_group 1;" ::: "memory");
        __syncthreads();
        if (ch + 2 < 32) loadChunk((ch + 2) % 3, ch + 2);
        else CP_COMMIT();                       // keep wait_group count valid
        computeChunk(ch % 3);
    }

    const int gr = lane >> 2, qd = lane & 3;

    if (CLSD) {
        // ---- fused classifier layer 2: partial d += relu(acc+b1).w2 ----
        float p[4][2];
#pragma unroll
        for (int i = 0; i < 4; i++) { p[i][0] = 0.f; p[i][1] = 0.f; }
        const float* w2 = w2p + (long)z * H;
#pragma unroll
        for (int j = 0; j < 4; j++) {
            const long c = n0 + wn * 32 + j * 8 + qd * 2;
            const float2 w2v = *(const float2*)&w2[c];
            const float2 bv = *(const float2*)&bias[c];
#pragma unroll
            for (int i = 0; i < 4; i++) {
                const float h0 = fmaxf(acc[i][j][0] + bv.x, 0.f);
                const float h1 = fmaxf(acc[i][j][1] + bv.y, 0.f);
                p[i][0] += h0 * w2v.x + h1 * w2v.y;
                const float h2 = fmaxf(acc[i][j][2] + bv.x, 0.f);
                const float h3 = fmaxf(acc[i][j][3] + bv.y, 0.f);
                p[i][1] += h2 * w2v.x + h3 * w2v.y;
            }
        }
#pragma unroll
        for (int i = 0; i < 4; i++) {
            p[i][0] += __shfl_xor_sync(~0u, p[i][0], 1);
            p[i][0] += __shfl_xor_sync(~0u, p[i][0], 2);
            p[i][1] += __shfl_xor_sync(~0u, p[i][1], 1);
            p[i][1] += __shfl_xor_sync(~0u, p[i][1], 2);
            if (qd == 0) {
                const long r = m0 + wm * 64 + i * 16 + gr;
                atomicAdd(&C[r * S + z], p[i][0]);
                atomicAdd(&C[(r + 8) * S + z], p[i][1]);
            }
        }
    } else {
        // ---- standard epilogue ----
#pragma unroll
        for (int j = 0; j < 4; j++) {
            const long c = n0 + wn * 32 + j * 8 + qd * 2;
            float2 bv = make_float2(0.f, 0.f);
            if (BIAS) bv = *(const float2*)&bias[c];
#pragma unroll
            for (int i = 0; i < 4; i++) {
                const long r0 = m0 + wm * 64 + i * 16 + gr;
                float2 v0 = make_float2(acc[i][j][0] + bv.x, acc[i][j][1] + bv.y);
                float2 v1 = make_float2(acc[i][j][2] + bv.x, acc[i][j][3] + bv.y);
                if (RELU) {
                    v0.x = fmaxf(v0.x, 0.f); v0.y = fmaxf(v0.y, 0.f);
                    v1.x = fmaxf(v1.x, 0.f); v1.y = fmaxf(v1.y, 0.f);
                }
                *(float2*)&C[r0 * ldc + c] = v0;
                *(float2*)&C[(r0 + 8) * ldc + c] = v1;
            }
        }
    }
}

// =============================================================================
// fp32 -> bf16 hi/lo split (vectorized by 4)
// =============================================================================
__device__ __forceinline__ void store_split4(float4 v, __nv_bfloat16* hi,
                                             __nv_bfloat16* lo, long i4) {
    __nv_bfloat16 h0 = __float2bfloat16(v.x), h1 = __float2bfloat16(v.y);
    __nv_bfloat16 h2 = __float2bfloat16(v.z), h3 = __float2bfloat16(v.w);
    __nv_bfloat162 a, b;
    a.x = h0; a.y = h1; b.x = h2; b.y = h3;
    ((__nv_bfloat162*)hi)[2 * i4] = a; ((__nv_bfloat162*)hi)[2 * i4 + 1] = b;
    a.x = __float2bfloat16(v.x - __bfloat162float(h0));
    a.y = __float2bfloat16(v.y - __bfloat162float(h1));
    b.x = __float2bfloat16(v.z - __bfloat162float(h2));
    b.y = __float2bfloat16(v.w - __bfloat162float(h3));
    ((__nv_bfloat162*)lo)[2 * i4] = a; ((__nv_bfloat162*)lo)[2 * i4 + 1] = b;
}

__global__ void split4(const float* __restrict__ src, __nv_bfloat16* __restrict__ hi,
                       __nv_bfloat16* __restrict__ lo, long n4)
{
    const long i = (long)blockIdx.x * 256 + threadIdx.x;
    if (i >= n4) return;
    store_split4(((const float4*)src)[i], hi, lo, i);
}

// 1024x1024 transpose + split: dst[c][r] = src[r][c]
__global__ void tsplit(const float* __restrict__ src, __nv_bfloat16* __restrict__ hi,
                       __nv_bfloat16* __restrict__ lo)
{
    __shared__ float t[32][33];
    const int bx = blockIdx.x * 32, by = blockIdx.y * 32;
    const int tx = threadIdx.x;
    for (int j = threadIdx.y; j < 32; j += 8)
        t[j][tx] = src[(long)(by + j) * 1024 + bx + tx];
    __syncthreads();
    for (int j = threadIdx.y; j < 32; j += 8) {
        const float v = t[tx][j];
        const long o = (long)(bx + j) * 1024 + by + tx;
        __nv_bfloat16 h = __float2bfloat16(v);
        hi[o] = h;
        lo[o] = __float2bfloat16(v - __bfloat162float(h));
    }
}

// avsplit: fusion = 0.5*(audio+video); split fusion, audio, video -> x hi/lo
__global__ void avsplit()
{
    const long i = (long)blockIdx.x * 256 + threadIdx.x;
    const long n4 = (long)B * D / 4;
    float4 a = ((const float4*)g_av)[i];
    float4 v = ((const float4*)g_av)[n4 + i];
    float4 f = make_float4(0.5f * (a.x + v.x), 0.5f * (a.y + v.y),
                           0.5f * (a.z + v.z), 0.5f * (a.w + v.w));
    store_split4(f, g_x_hi, g_x_lo, i);
    store_split4(a, g_x_hi, g_x_lo, n4 + i);
    store_split4(v, g_x_hi, g_x_lo, 2 * n4 + i);
}

__global__ void zero_d()
{
    g_d[blockIdx.x * 256 + threadIdx.x] = 0.f;
}

__global__ void pack_bias(const float* __restrict__ b0, const float* __restrict__ b1,
                          const float* __restrict__ b2)
{
    const int i = blockIdx.x * 256 + threadIdx.x;   // 0..1535
    const int hh = i >> 9, j = i & 511;
    g_hbias[i] = hh == 0 ? b0[j] : (hh == 1 ? b1[j] : b2[j]);
}

// =============================================================================
// bias-derived vectors (fp32, tiny)
// =============================================================================
__global__ void vec_pre(const float* __restrict__ in_proj_w,
                        const float* __restrict__ in_proj_b,
                        const float* __restrict__ out_w,
                        const float* __restrict__ out_b)
{
    const int i = blockIdx.x * 256 + threadIdx.x;
    const float* wq = in_proj_w;
    const float* wk = in_proj_w + (long)D * D;
    const float* bq = in_proj_b;
    const float* bk = in_proj_b + D;
    const float* bv = in_proj_b + 2 * D;
    float vq = 0.f, vk = 0.f, bc = 0.f;
    for (int e = 0; e < D; e++) {
        vq = fmaf(bq[e], wk[(long)e * D + i], vq);
        vk = fmaf(bk[e], wq[(long)e * D + i], vk);
        bc = fmaf(out_w[(long)i * D + e], bv[e], bc);
    }
    g_vq[i] = vq; g_vk[i] = vk; g_bcomb[i] = bc + out_b[i];
    if (i == 0) {
        float c = 0.f;
        for (int e = 0; e < D; e++) c = fmaf(bq[e], bk[e], c);
        g_c0 = c;
    }
}

// =============================================================================
// Per-batch attention (fp32); reads g_d (pre-bias logits), writes qv hi/lo
// =============================================================================
__global__ void __launch_bounds__(256) attn_kernel(
    const float* __restrict__ q, const float* __restrict__ cls_b2,
    float* __restrict__ out)
{
    const int b = blockIdx.x;
    __shared__ float qs[32][132];
    __shared__ float qms[32][132];
    __shared__ float sc[32][33];
    __shared__ float vks[128];
    __shared__ float dd[32], rk[32], wa[32], wvv[32], da[16], dv[16];

    const int tid = threadIdx.x;
    const int s = tid >> 3;
    const int tb = tid & 7;
    const float* qb = q + (long)b * S * D;
    const float* qmb = g_qM + (long)b * S * D;

    if (tid < 32) dd[tid] = fmaxf(g_d[b * S + tid] + cls_b2[tid], 0.f);

    float racc[4] = {0.f, 0.f, 0.f, 0.f};
    float rkacc = 0.f;

    for (int c = 0; c < D; c += 128) {
#pragma unroll
        for (int i = 0; i < 4; i++) {
            const int f = tid + 256 * i;
            const int r = f >> 5;
            const int c4 = (f & 31) << 2;
            *(float4*)&qs[r][c4] = *(const float4*)&qb[(long)r * D + c + c4];
            *(float4*)&qms[r][c4] = *(const float4*)&qmb[(long)r * D + c + c4];
        }
        if (tid < 32) *(float4*)&vks[tid * 4] = *(const float4*)&g_vk[c + tid * 4];
        __syncthreads();

#pragma unroll 4
        for (int k = 0; k < 128; k++) {
            const float av = qms[s][k];
#pragma unroll
            for (int j = 0; j < 4; j++)
                racc[j] = fmaf(av, qs[tb + 8 * j][k], racc[j]);
        }
        if (tid < 32) {
            float r2 = 0.f;
#pragma unroll 4
            for (int k = 0; k < 128; k++) r2 = fmaf(qs[tid][k], vks[k], r2);
            rkacc += r2;
        }
        __syncthreads();
    }

#pragma unroll
    for (int j = 0; j < 4; j++) sc[s][tb + 8 * j] = racc[j];
    if (tid < 32) rk[tid] = rkacc;
    __syncthreads();

    const int w = tid >> 5, lane = tid & 31;
    const float inv_sqrtD = 0.03125f;
    for (int rr = w * 4; rr < w * 4 + 4; rr++) {
        float v = (sc[rr][lane] + rk[rr] + g_c0) * inv_sqrtD;
        float mx = v;
#pragma unroll
        for (int o = 16; o > 0; o >>= 1) mx = fmaxf(mx, __shfl_xor_sync(~0u, mx, o));
        float e = __expf(v - mx);
        float sum = e;
#pragma unroll
        for (int o = 16; o > 0; o >>= 1) sum += __shfl_xor_sync(~0u, sum, o);
        sc[rr][lane] = e / sum;
    }
    __syncthreads();

    if (tid < 32) {
        const bool isA = tid < 16;
        const int i = tid & 15;
        float v = dd[tid];
        float mx = v;
#pragma unroll
        for (int o = 8; o > 0; o >>= 1) mx = fmaxf(mx, __shfl_xor_sync(~0u, mx, o));
        float e = __expf(v - mx);
        float sum = e;
#pragma unroll
        for (int o = 8; o > 0; o >>= 1) sum += __shfl_xor_sync(~0u, sum, o);
        const float p = e / sum;
        if (isA) da[i] = p; else dv[i] = p;
        const long bse = 3L * B * F;
        if (isA) out[bse + (long)b * P + i] = p;
        else     out[bse + (long)B * P + (long)b * P + i] = p;
    }
    __syncthreads();

    if (tid < 32) {
        float a = 0.f, v2 = 0.f;
#pragma unroll
        for (int ss = 0; ss < 16; ss++) a = fmaf(da[ss], sc[ss][tid], a);
#pragma unroll
        for (int ss = 0; ss < 16; ss++) v2 = fmaf(dv[ss], sc[16 + ss][tid], v2);
        wa[tid] = a;
        wvv[tid] = v2;
    }
    __syncthreads();

#pragma unroll
    for (int i = 0; i < 4; i++) {
        const int col = tid + 256 * i;
        float a = 0.f, v2 = 0.f;
#pragma unroll
        for (int t = 0; t < 32; t++) {
            const float x = qb[(long)t * D + col];
            a = fmaf(wa[t], x, a);
            v2 = fmaf(wvv[t], x, v2);
        }
        const long ia = (long)b * D + col;
        const long iv = (long)B * D + ia;
        __nv_bfloat16 h = __float2bfloat16(a);
        g_qv_hi[ia] = h;
        g_qv_lo[ia] = __float2bfloat16(a - __bfloat162float(h));
        h = __float2bfloat16(v2);
        g_qv_hi[iv] = h;
        g_qv_lo[iv] = __float2bfloat16(v2 - __bfloat162float(h));
    }
}

__global__ void __launch_bounds__(128) ln_relu(
    const float* __restrict__ gm0, const float* __restrict__ be0,
    const float* __restrict__ gm1, const float* __restrict__ be1,
    const float* __restrict__ gm2, const float* __restrict__ be2,
    float* __restrict__ out)
{
    const int head = blockIdx.y, b = blockIdx.x, tid = threadIdx.x;
    const float* gm = head == 0 ? gm0 : (head == 1 ? gm1 : gm2);
    const float* be = head == 0 ? be0 : (head == 1 ? be1 : be2);
    const float* y = g_y + ((long)head * B + b) * F;

    float4 v = *(const float4*)&y[tid * 4];
    float s = v.x + v.y + v.z + v.w;
    float sq = v.x * v.x + v.y * v.y + v.z * v.z + v.w * v.w;
#pragma unroll
    for (int o = 16; o > 0; o >>= 1) {
        s += __shfl_xor_sync(~0u, s, o);
        sq += __shfl_xor_sync(~0u, sq, o);
    }
    __shared__ float ss[4], ssq[4];
    const int w = tid >> 5;
    if ((tid & 31) == 0) { ss[w] = s; ssq[w] = sq; }
    __syncthreads();
    s = ss[0] + ss[1] + ss[2] + ss[3];
    sq = ssq[0] + ssq[1] + ssq[2] + ssq[3];
    const float mean = s * (1.f / F);
    const float var = sq * (1.f / F) - mean * mean;
    const float rstd = rsqrtf(var + 1e-5f);

    float4 g4 = *(const float4*)&gm[tid * 4];
    float4 b4 = *(const float4*)&be[tid * 4];
    float4 o4;
    o4.x = fmaxf((v.x - mean) * rstd * g4.x + b4.x, 0.f);
    o4.y = fmaxf((v.y - mean) * rstd * g4.y + b4.y, 0.f);
    o4.z = fmaxf((v.z - mean) * rstd * g4.z + b4.z, 0.f);
    o4.w = fmaxf((v.w - mean) * rstd * g4.w + b4.w, 0.f);
    *(float4*)&out[((long)head * B + b) * F + tid * 4] = o4;
}

}  // namespace raff

// =============================================================================
// Launch
// =============================================================================
extern "C" void kernel_launch(void* const* d_in, const int* in_sizes, int n_in,
                              void* d_out, int out_size)
{
    using namespace raff;
    (void)in_sizes; (void)n_in; (void)out_size;

    const float* q         = (const float*)d_in[0];
    const float* in_proj_w = (const float*)d_in[1];
    const float* in_proj_b = (const float*)d_in[2];
    const float* out_w     = (const float*)d_in[3];
    const float* out_b     = (const float*)d_in[4];
    const float* cls_w1    = (const float*)d_in[5];
    const float* cls_b1    = (const float*)d_in[6];
    const float* cls_w2    = (const float*)d_in[7];
    const float* cls_b2    = (const float*)d_in[8];
    const float* fus_w     = (const float*)d_in[9];
    const float* fus_b     = (const float*)d_in[10];
    const float* fus_g     = (const float*)d_in[11];
    const float* fus_be    = (const float*)d_in[12];
    const float* pa_w      = (const float*)d_in[13];
    const float* pa_b      = (const float*)d_in[14];
    const float* pa_g      = (const float*)d_in[15];
    const float* pa_be     = (const float*)d_in[16];
    const float* pv_w      = (const float*)d_in[17];
    const float* pv_b      = (const float*)d_in[18];
    const float* pv_g      = (const float*)d_in[19];
    const float* pv_be     = (const float*)d_in[20];
    float* out = (float*)d_out;

    float *pMC, *pqM, *pd, *pav, *py, *pvq, *pbcomb, *phb;
    __nv_bfloat16 *qhi, *qlo, *w1hi, *w1lo, *uhi, *ulo, *vhi, *vlo,
        *mchi, *mclo, *qvhi, *qvlo, *xhi, *xlo, *hwhi, *hwlo;
    cudaGetSymbolAddress((void**)&pMC, g_MC);
    cudaGetSymbolAddress((void**)&pqM, g_qM);
    cudaGetSymbolAddress((void**)&pd, g_d);
    cudaGetSymbolAddress((void**)&pav, g_av);
    cudaGetSymbolAddress((void**)&py, g_y);
    cudaGetSymbolAddress((void**)&pvq, g_vq);
    cudaGetSymbolAddress((void**)&pbcomb, g_bcomb);
    cudaGetSymbolAddress((void**)&phb, g_hbias);
    cudaGetSymbolAddress((void**)&qhi, g_q_hi);
    cudaGetSymbolAddress((void**)&qlo, g_q_lo);
    cudaGetSymbolAddress((void**)&w1hi, g_w1_hi);
    cudaGetSymbolAddress((void**)&w1lo, g_w1_lo);
    cudaGetSymbolAddress((void**)&uhi, g_u_hi);
    cudaGetSymbolAddress((void**)&ulo, g_u_lo);
    cudaGetSymbolAddress((void**)&vhi, g_v_hi);
    cudaGetSymbolAddress((void**)&vlo, g_v_lo);
    cudaGetSymbolAddress((void**)&mchi, g_mc_hi);
    cudaGetSymbolAddress((void**)&mclo, g_mc_lo);
    cudaGetSymbolAddress((void**)&qvhi, g_qv_hi);
    cudaGetSymbolAddress((void**)&qvlo, g_qv_lo);
    cudaGetSymbolAddress((void**)&xhi, g_x_hi);
    cudaGetSymbolAddress((void**)&xlo, g_x_lo);
    cudaGetSymbolAddress((void**)&hwhi, g_hw_hi);
    cudaGetSymbolAddress((void**)&hwlo, g_hw_lo);

    cudaFuncSetAttribute((const void*)bsgemm<false, false, false>,
                         cudaFuncAttributeMaxDynamicSharedMemorySize, GEMM_SMEM);
    cudaFuncSetAttribute((const void*)bsgemm<false, true, false>,
                         cudaFuncAttributeMaxDynamicSharedMemorySize, GEMM_SMEM);
    cudaFuncSetAttribute((const void*)bsgemm<false, false, true>,
                         cudaFuncAttributeMaxDynamicSharedMemorySize, GEMM_SMEM);

    // 1) tiny precomputations
    vec_pre<<<D / 256, 256>>>(in_proj_w, in_proj_b, out_w, out_b);
    pack_bias<<<6, 256>>>(fus_b, pa_b, pv_b);
    zero_d<<<B * S / 256, 256>>>();

    // 2) conversions of inputs
    split4<<<(int)(NQ / 4 / 256), 256>>>(q, qhi, qlo, NQ / 4);
    split4<<<(int)((long)S * H * D / 4 / 256), 256>>>(cls_w1, w1hi, w1lo,
                                                      (long)S * H * D / 4);
    split4<<<D * D / 4 / 256, 256>>>(out_w, uhi + (long)D * D, ulo + (long)D * D,
                                     D * D / 4);
    split4<<<F * D / 4 / 256, 256>>>(fus_w, hwhi, hwlo, (long)F * D / 4);
    split4<<<F * D / 4 / 256, 256>>>(pa_w, hwhi + (long)F * D, hwlo + (long)F * D,
                                     (long)F * D / 4);
    split4<<<F * D / 4 / 256, 256>>>(pv_w, hwhi + 2L * F * D, hwlo + 2L * F * D,
                                     (long)F * D / 4);
    tsplit<<<dim3(32, 32), dim3(32, 8)>>>(in_proj_w + (long)D * D, uhi, ulo);    // WkT
    tsplit<<<dim3(32, 32), dim3(32, 8)>>>(in_proj_w, vhi, vlo);                  // WqT
    tsplit<<<dim3(32, 32), dim3(32, 8)>>>(in_proj_w + 2L * D * D,
                                          vhi + (long)D * D, vlo + (long)D * D); // WvT

    // 3) [Mt; Cov] in one z=2 launch: z0 = WkT*WqT^T, z1 = out_w*WvT^T
    bsgemm<false, false, false><<<dim3(8, 8, 2), 256, GEMM_SMEM>>>(
        uhi, ulo, D, (long)D * D, vhi, vlo, (long)D * D,
        pMC, D, (long)D * D, nullptr, 0L, nullptr);
    split4<<<2 * D * D / 4 / 256, 256>>>(pMC, mchi, mclo, 2 * D * D / 4);

    // 4) qM = q * Mt^T + vq   [65536 x 1024 x 1024]
    bsgemm<false, true, false><<<dim3(8, 512), 256, GEMM_SMEM>>>(
        qhi, qlo, (long)D, 0L, mchi, mclo, 0L, pqM, D, 0L, pvq, 0L, nullptr);

    // 5) classifier: fused h = relu(q w1^T + b1), d += h.w2 (atomic)
    bsgemm<false, false, true><<<dim3(4, 16, 32), 256, GEMM_SMEM>>>(
        qhi, qlo, (long)S * D, (long)D, w1hi, w1lo, (long)H * D,
        pd, S, 0L, cls_b1, (long)H, cls_w2);

    // 6) attention + softmaxes + weighted q sums -> qv hi/lo
    attn_kernel<<<B, 256>>>(q, cls_b2, out);

    // 7) [audio; video] = qv * Cov^T + bcomb
    bsgemm<false, true, false><<<dim3(8, 32), 256, GEMM_SMEM>>>(
        qvhi, qvlo, (long)D, 0L, mchi + (long)D * D, mclo + (long)D * D, 0L,
        pav, D, 0L, pbcomb, 0L, nullptr);

    // 8) fusion + splits of head inputs
    avsplit<<<(int)((long)B * D / 4 / 256), 256>>>();

    // 9) heads: one z=3 launch  y = x * W^T + b  [2048 x 512 x 1024]
    bsgemm<false, true, false><<<dim3(4, 16, 3), 256, GEMM_SMEM>>>(
        xhi, xlo, (long)D, (long)B * D, hwhi, hwlo, (long)F * D,
        py, F, (long)B * F, phb, (long)F, nullptr);

    // 10) LayerNorm + ReLU -> final outputs
    ln_relu<<<dim3(B, 3), 128>>>(fus_g, fus_be, pa_g, pa_be, pv_g, pv_be, out);
}